// round 7
// baseline (speedup 1.0000x reference)
#include <cuda_runtime.h>
#include <cuda_fp16.h>
#include <cstdint>

#define BATCH 4
#define SEQ   2048
#define DIM   2048
#define M_TOT (BATCH*SEQ)     // 8192
#define NCH   16
#define CHLEN (SEQ/NCH)       // 128

#define BM 128
#define BN 128
#define BK 64
#define NSTAGE 3
#define NTHREADS 128          // 4 warps, 2x2 grid of 64x64 warp tiles

// ---------------- scratch (device globals; no allocation allowed) ----------------
__device__ __align__(16) __half g_Xq [M_TOT*DIM];        // quantized x (integer k as fp16)
__device__ __align__(16) __half g_Wi [DIM*DIM];          // w_i^T  [N][K]
__device__ __align__(16) __half g_Wf [DIM*DIM];
__device__ __align__(16) __half g_Wg [DIM*DIM];
__device__ __align__(16) __half g_Wo2[DIM*2*DIM];        // w_o duplicated over K=4096 (hi|lo)
__device__ __align__(16) float  g_Yi [M_TOT*DIM];        // raw i   (later: h)
__device__ __align__(16) float  g_Yf [M_TOT*DIM];        // f = sigmoid(raw)
__device__ __align__(16) float  g_Yg [M_TOT*DIM];        // gsw = g*sigmoid(g)
__device__ __align__(16) __half g_A2 [M_TOT*2*DIM];      // (o*s_o) split hi|lo
__device__ float g_P [NCH*BATCH*DIM];
__device__ float g_Hc[NCH*BATCH*DIM];
__device__ float g_Cr[NCH*BATCH*DIM];

// ---------------- PTX helpers ----------------
__device__ __forceinline__ void cp16(uint32_t s, const void* g) {
    asm volatile("cp.async.cg.shared.global [%0], [%1], 16;\n" :: "r"(s), "l"(g));
}
__device__ __forceinline__ void cp_commit() { asm volatile("cp.async.commit_group;\n"); }
template<int N> __device__ __forceinline__ void cp_wait() {
    asm volatile("cp.async.wait_group %0;\n" :: "n"(N));
}
__device__ __forceinline__ void ldsm4(uint32_t& r0, uint32_t& r1, uint32_t& r2, uint32_t& r3, uint32_t a) {
    asm volatile("ldmatrix.sync.aligned.m8n8.x4.shared.b16 {%0,%1,%2,%3},[%4];\n"
                 : "=r"(r0), "=r"(r1), "=r"(r2), "=r"(r3) : "r"(a));
}
__device__ __forceinline__ void mma16816(float* c, const uint32_t* a, const uint32_t* b) {
    asm volatile("mma.sync.aligned.m16n8k16.row.col.f32.f16.f16.f32 "
                 "{%0,%1,%2,%3},{%4,%5,%6,%7},{%8,%9},{%0,%1,%2,%3};\n"
                 : "+f"(c[0]), "+f"(c[1]), "+f"(c[2]), "+f"(c[3])
                 : "r"(a[0]), "r"(a[1]), "r"(a[2]), "r"(a[3]), "r"(b[0]), "r"(b[1]));
}
// swizzled half-index inside a BMxBK stage (rows of 64 halfs = 8 chunks of 16B)
__device__ __forceinline__ uint32_t swz(int row, int k) {
    return (uint32_t)(row*BK + ((((k >> 3) ^ (row & 7)) << 3) | (k & 7)));
}
__device__ __forceinline__ float fsig(float x) {   // fast sigmoid via MUFU ex2 path
    return 1.f / (1.f + __expf(-x));
}

// ---------------- elementwise kernels ----------------
__global__ void k_quant(const float* __restrict__ hs) {
    int i = blockIdx.x * 256 + threadIdx.x;
    const float4 v = ((const float4*)hs)[i];
    __half h[4];
    h[0] = __float2half_rn(rintf(v.x * 256.f));
    h[1] = __float2half_rn(rintf(v.y * 256.f));
    h[2] = __float2half_rn(rintf(v.z * 256.f));
    h[3] = __float2half_rn(rintf(v.w * 256.f));
    ((uint2*)g_Xq)[i] = *(uint2*)h;
}

__global__ void k_transpose(const float* __restrict__ wi, const float* __restrict__ wf,
                            const float* __restrict__ wg) {
    __shared__ float tile[32][33];
    int z = blockIdx.z;
    const float* src = (z == 0) ? wi : (z == 1) ? wf : wg;
    __half* dst = (z == 0) ? g_Wi : (z == 1) ? g_Wf : g_Wg;
    int k0 = blockIdx.y * 32, n0 = blockIdx.x * 32;
    int tx = threadIdx.x, ty = threadIdx.y;     // 32 x 8
    #pragma unroll
    for (int j = 0; j < 32; j += 8)
        tile[ty + j][tx] = src[(size_t)(k0 + ty + j) * DIM + n0 + tx];
    __syncthreads();
    #pragma unroll
    for (int j = 0; j < 32; j += 8)
        dst[(size_t)(n0 + ty + j) * DIM + k0 + tx] = __float2half_rn(tile[tx][ty + j]);
}

__global__ void k_wo(const float* __restrict__ wo) {
    int idx = blockIdx.x * 256 + threadIdx.x;     // over DIM*DIM
    int n = idx >> 11, k = idx & 2047;
    __half h = __float2half_rn(wo[idx]);          // ternary: exact
    g_Wo2[(size_t)n * (2*DIM) + k]        = h;    // multiplies o_hi
    g_Wo2[(size_t)n * (2*DIM) + DIM + k]  = h;    // multiplies o_lo
}

// ---------------- GEMM: C[M,N] = A[M,K] * B[N,K]^T (fp16 in, fp32 acc) ----------------
// 4 warps, 64x64 warp tiles, 3-stage cp.async ring, per-warp ks-order skew.
__global__ void __launch_bounds__(NTHREADS, 2) k_gemm(
    const __half* __restrict__ A,
    const __half* __restrict__ B0, const __half* __restrict__ B1,
    const __half* __restrict__ B2,
    float* C0, float* C1, float* C2,
    const float* s0, const float* s1, const float* s2,
    int K, int mode)
{
    extern __shared__ __half sm[];
    constexpr int STAGE_H = BM * BK + BN * BK;    // halfs per stage
    int z = blockIdx.z;
    const __half* Bw = (z == 0) ? B0 : (z == 1) ? B1 : B2;
    float* Cc        = (z == 0) ? C0 : (z == 1) ? C1 : C2;
    const float* sp  = (z == 0) ? s0 : (z == 1) ? s1 : s2;

    int bm = blockIdx.y * BM, bn = blockIdx.x * BN;
    const __half* Ag = A  + (size_t)bm * K;
    const __half* Bg = Bw + (size_t)bn * K;
    int tid = threadIdx.x;
    uint32_t sbase = (uint32_t)__cvta_generic_to_shared(sm);
    int KT = K / BK;

    int lane = tid & 31, w = tid >> 5;
    int wm = (w >> 1) * 64, wn = (w & 1) * 64;   // 2x2 warp grid, warp tile 64x64
    int g = lane >> 2, t2 = (lane & 3) << 1;
    int r = lane & 7, sub = lane >> 3;

    float acc[4][8][4];
    #pragma unroll
    for (int a = 0; a < 4; a++)
        #pragma unroll
        for (int b = 0; b < 8; b++)
            #pragma unroll
            for (int c = 0; c < 4; c++) acc[a][b][c] = 0.f;

    // stage loader: 128 threads, 8 x 16B each for A and B
    auto load = [&](int st, int kt) {
        int kb = kt * BK;
        uint32_t sA = sbase + (uint32_t)(st * STAGE_H) * 2;
        uint32_t sB = sA + (uint32_t)(BM * BK) * 2;
        #pragma unroll
        for (int i = 0; i < 8; i++) {
            int v = tid + i * NTHREADS;
            int row = v >> 3, ch = v & 7;
            uint32_t so = (uint32_t)(swz(row, ch * 8) * 2);
            cp16(sA + so, Ag + (size_t)row * K + kb + ch * 8);
            cp16(sB + so, Bg + (size_t)row * K + kb + ch * 8);
        }
    };

    // prologue: fill NSTAGE-1 stages
    load(0, 0); cp_commit();
    load(1, 1); cp_commit();

    for (int kt = 0; kt < KT; kt++) {
        cp_wait<NSTAGE - 2>();       // stage kt resident
        __syncthreads();
        if (kt + NSTAGE - 1 < KT) load((kt + NSTAGE - 1) % NSTAGE, kt + NSTAGE - 1);
        cp_commit();                 // uniform group counting

        int stb = (kt % NSTAGE) * STAGE_H;
        uint32_t sA = sbase + (uint32_t)stb * 2;
        uint32_t sB = sA + (uint32_t)(BM * BK) * 2;
        // per-warp skewed ks order: decorrelates ldsm phases across warps so the
        // SMSP's other warp keeps the tensor pipe fed during this warp's loads
        #pragma unroll
        for (int j = 0; j < 4; j++) {
            int ks = (j + w) & 3;
            int ko = ks * 16;
            uint32_t a[4][4], b[8][2];
            #pragma unroll
            for (int mi = 0; mi < 4; mi++) {
                int row = wm + mi * 16 + r + ((sub & 1) << 3);
                int kk  = ko + ((sub >> 1) << 3);
                ldsm4(a[mi][0], a[mi][1], a[mi][2], a[mi][3],
                      sA + (uint32_t)(swz(row, kk) * 2));
            }
            #pragma unroll
            for (int p = 0; p < 4; p++) {
                int rown = wn + p * 16 + r + ((sub >> 1) << 3);
                int kk   = ko + ((sub & 1) << 3);
                ldsm4(b[2*p][0], b[2*p][1], b[2*p+1][0], b[2*p+1][1],
                      sB + (uint32_t)(swz(rown, kk) * 2));
            }
            #pragma unroll
            for (int mi = 0; mi < 4; mi++)
                #pragma unroll
                for (int ni = 0; ni < 8; ni++)
                    mma16816(acc[mi][ni], a[mi], b[ni]);
        }
    }

    const float inv256 = 1.f / 256.f;
    #pragma unroll
    for (int mi = 0; mi < 4; mi++) {
        #pragma unroll
        for (int ni = 0; ni < 8; ni++) {
            int row = bm + wm + mi * 16 + g;
            int col = bn + wn + ni * 8 + t2;
            float* c = acc[mi][ni];
            if (mode == 0) {
                float sa = sp[col] * inv256, sb = sp[col + 1] * inv256;
                float v0 = c[0] * sa, v1 = c[1] * sb, v2 = c[2] * sa, v3 = c[3] * sb;
                if (z == 1) {          // forget gate: store sigmoid
                    v0 = fsig(v0); v1 = fsig(v1); v2 = fsig(v2); v3 = fsig(v3);
                } else if (z == 2) {   // output gate: store swish
                    v0 = v0 * fsig(v0); v1 = v1 * fsig(v1);
                    v2 = v2 * fsig(v2); v3 = v3 * fsig(v3);
                }
                Cc[(size_t)row * DIM + col]           = v0;
                Cc[(size_t)row * DIM + col + 1]       = v1;
                Cc[(size_t)(row + 8) * DIM + col]     = v2;
                Cc[(size_t)(row + 8) * DIM + col + 1] = v3;
            } else {  // to_fixed(acc)
                Cc[(size_t)row * DIM + col]           = rintf(c[0] * 256.f) * inv256;
                Cc[(size_t)row * DIM + col + 1]       = rintf(c[1] * 256.f) * inv256;
                Cc[(size_t)(row + 8) * DIM + col]     = rintf(c[2] * 256.f) * inv256;
                Cc[(size_t)(row + 8) * DIM + col + 1] = rintf(c[3] * 256.f) * inv256;
            }
        }
    }
}

// ---------------- chunked linear-recurrence scan (f precomputed) ----------------
__global__ void k_scan1() {
    int d4 = blockIdx.x * 128 + threadIdx.x;        // float4 index within DIM/4
    int c = blockIdx.y, b = blockIdx.z;
    size_t base = ((size_t)(b * SEQ + c * CHLEN)) * (DIM/4) + d4;
    const float4* Yf4 = (const float4*)g_Yf;
    const float4* Yi4 = (const float4*)g_Yi;
    float4 P = make_float4(1.f,1.f,1.f,1.f), H = make_float4(0.f,0.f,0.f,0.f);
    #pragma unroll 4
    for (int t = 0; t < CHLEN; t++) {
        float4 f  = Yf4[base + (size_t)t * (DIM/4)];
        float4 yi = Yi4[base + (size_t)t * (DIM/4)];
        P.x *= f.x; P.y *= f.y; P.z *= f.z; P.w *= f.w;
        H.x = fmaf(f.x, H.x, (1.f - f.x) * yi.x);
        H.y = fmaf(f.y, H.y, (1.f - f.y) * yi.y);
        H.z = fmaf(f.z, H.z, (1.f - f.z) * yi.z);
        H.w = fmaf(f.w, H.w, (1.f - f.w) * yi.w);
    }
    int o = (c * BATCH + b) * (DIM/4) + d4;
    ((float4*)g_P)[o] = P; ((float4*)g_Hc)[o] = H;
}

__global__ void k_scan2() {
    int idx = blockIdx.x * 256 + threadIdx.x;   // 0..B*DIM/4-1
    float4 h = make_float4(0.f,0.f,0.f,0.f);
    #pragma unroll
    for (int c = 0; c < NCH; c++) {
        int o = c * (BATCH * DIM / 4) + idx;
        ((float4*)g_Cr)[o] = h;
        float4 P = ((const float4*)g_P)[o];
        float4 Hc = ((const float4*)g_Hc)[o];
        h.x = fmaf(P.x, h.x, Hc.x); h.y = fmaf(P.y, h.y, Hc.y);
        h.z = fmaf(P.z, h.z, Hc.z); h.w = fmaf(P.w, h.w, Hc.w);
    }
}

__global__ void k_scan3() {
    int d4 = blockIdx.x * 128 + threadIdx.x;
    int c = blockIdx.y, b = blockIdx.z;
    size_t base = ((size_t)(b * SEQ + c * CHLEN)) * (DIM/4) + d4;
    const float4* Yf4 = (const float4*)g_Yf;
    float4* Yi4 = (float4*)g_Yi;
    float4 h = ((const float4*)g_Cr)[(c * BATCH + b) * (DIM/4) + d4];
    #pragma unroll 4
    for (int t = 0; t < CHLEN; t++) {
        float4 f  = Yf4[base + (size_t)t * (DIM/4)];
        float4 yi = Yi4[base + (size_t)t * (DIM/4)];
        h.x = fmaf(f.x, h.x, (1.f - f.x) * yi.x);
        h.y = fmaf(f.y, h.y, (1.f - f.y) * yi.y);
        h.z = fmaf(f.z, h.z, (1.f - f.z) * yi.z);
        h.w = fmaf(f.w, h.w, (1.f - f.w) * yi.w);
        Yi4[base + (size_t)t * (DIM/4)] = h;   // overwrite i-buffer with h
    }
}

// ---------------- RMSNorm * weight * gsw * s_o -> hi/lo fp16 split ----------------
__global__ void k_norm(const float* __restrict__ so, const float* __restrict__ gnw) {
    int m = blockIdx.x;
    int tid = threadIdx.x;
    size_t b4 = (size_t)m * (DIM/4);
    const float4* Yi4 = (const float4*)g_Yi;
    float4 hv[2];
    float ss = 0.f;
    #pragma unroll
    for (int j = 0; j < 2; j++) {
        hv[j] = Yi4[b4 + tid + j * 256];
        ss += hv[j].x*hv[j].x + hv[j].y*hv[j].y + hv[j].z*hv[j].z + hv[j].w*hv[j].w;
    }
    #pragma unroll
    for (int o = 16; o; o >>= 1) ss += __shfl_xor_sync(0xffffffffu, ss, o);
    __shared__ float red[8];
    __shared__ float tot;
    if ((tid & 31) == 0) red[tid >> 5] = ss;
    __syncthreads();
    if (tid < 8) {
        float v = red[tid];
        #pragma unroll
        for (int o = 4; o; o >>= 1) v += __shfl_xor_sync(0xffu, v, o);
        if (tid == 0) tot = v;
    }
    __syncthreads();
    float rms = rsqrtf(tot * (1.f / DIM) + 1e-5f);
    const float4* Yg4 = (const float4*)g_Yg;
    const float4* so4 = (const float4*)so;
    const float4* gn4 = (const float4*)gnw;
    #pragma unroll
    for (int j = 0; j < 2; j++) {
        int e4 = tid + j * 256;
        float4 gv = Yg4[b4 + e4];      // already g*sigmoid(g)
        float4 sv = so4[e4];
        float4 wv = gn4[e4];
        float q[4];
        q[0] = hv[j].x * rms * wv.x * gv.x * sv.x;
        q[1] = hv[j].y * rms * wv.y * gv.y * sv.y;
        q[2] = hv[j].z * rms * wv.z * gv.z * sv.z;
        q[3] = hv[j].w * rms * wv.w * gv.w * sv.w;
        __half hi[4]; __half lo[4];
        #pragma unroll
        for (int u = 0; u < 4; u++) {
            hi[u] = __float2half_rn(q[u]);
            lo[u] = __float2half_rn(q[u] - __half2float(hi[u]));
        }
        ((uint2*)(g_A2 + (size_t)m * (2*DIM)))[e4]            = *(uint2*)hi;
        ((uint2*)(g_A2 + (size_t)m * (2*DIM) + DIM))[e4]      = *(uint2*)lo;
    }
}

// ---------------- launch ----------------
extern "C" void kernel_launch(void* const* d_in, const int* in_sizes, int n_in,
                              void* d_out, int out_size) {
    const float* hs  = (const float*)d_in[0];
    const float* wi  = (const float*)d_in[1];
    const float* wf  = (const float*)d_in[2];
    const float* wg  = (const float*)d_in[3];
    const float* wo  = (const float*)d_in[4];
    const float* si  = (const float*)d_in[5];
    const float* sf  = (const float*)d_in[6];
    const float* sg  = (const float*)d_in[7];
    const float* so  = (const float*)d_in[8];
    const float* gnw = (const float*)d_in[9];

    __half *Xq, *Wi, *Wf, *Wg, *Wo2, *A2;
    float  *Yi, *Yf, *Yg;
    cudaGetSymbolAddress((void**)&Xq,  g_Xq);
    cudaGetSymbolAddress((void**)&Wi,  g_Wi);
    cudaGetSymbolAddress((void**)&Wf,  g_Wf);
    cudaGetSymbolAddress((void**)&Wg,  g_Wg);
    cudaGetSymbolAddress((void**)&Wo2, g_Wo2);
    cudaGetSymbolAddress((void**)&A2,  g_A2);
    cudaGetSymbolAddress((void**)&Yi,  g_Yi);
    cudaGetSymbolAddress((void**)&Yf,  g_Yf);
    cudaGetSymbolAddress((void**)&Yg,  g_Yg);

    const int smem = NSTAGE * (BM * BK + BN * BK) * 2;  // 96 KB
    cudaFuncSetAttribute(k_gemm, cudaFuncAttributeMaxDynamicSharedMemorySize, smem);

    k_quant<<<(M_TOT * DIM) / 1024, 256>>>(hs);
    k_transpose<<<dim3(DIM / 32, DIM / 32, 3), dim3(32, 8)>>>(wi, wf, wg);
    k_wo<<<(DIM * DIM) / 256, 256>>>(wo);

    // i/f/g projections: exact integer fp16 MMA; epilogue applies scale + sigmoid/swish
    k_gemm<<<dim3(DIM / BN, M_TOT / BM, 3), NTHREADS, smem>>>(
        Xq, Wi, Wf, Wg, Yi, Yf, Yg, si, sf, sg, DIM, 0);

    k_scan1<<<dim3(DIM / 512, NCH, BATCH), 128>>>();
    k_scan2<<<(BATCH * DIM / 4) / 256, 256>>>();
    k_scan3<<<dim3(DIM / 512, NCH, BATCH), 128>>>();

    k_norm<<<M_TOT, 256>>>(so, gnw);

    // output projection: split-fp16 (hi+lo), K_eff = 4096, to_fixed epilogue
    k_gemm<<<dim3(DIM / BN, M_TOT / BM, 1), NTHREADS, smem>>>(
        A2, Wo2, Wo2, Wo2, (float*)d_out, nullptr, nullptr,
        nullptr, nullptr, nullptr, 2 * DIM, 1);
}

// round 8
// speedup vs baseline: 1.0854x; 1.0854x over previous
#include <cuda_runtime.h>
#include <cuda_fp16.h>
#include <cstdint>

#define BATCH 4
#define SEQ   2048
#define DIM   2048
#define M_TOT (BATCH*SEQ)     // 8192
#define NCH   64
#define CHLEN (SEQ/NCH)       // 32

#define BM 128
#define BN 128
#define BK 64
#define NSTAGE 3
#define NTHREADS 128          // 4 warps, 2x2 grid of 64x64 warp tiles

// ---------------- scratch (device globals; no allocation allowed) ----------------
__device__ __align__(16) __half g_Xq [M_TOT*DIM];        // quantized x (integer k as fp16)
__device__ __align__(16) __half g_Wi [DIM*DIM];          // w_i^T  [N][K]
__device__ __align__(16) __half g_Wf [DIM*DIM];
__device__ __align__(16) __half g_Wg [DIM*DIM];
__device__ __align__(16) __half g_Wo2[DIM*2*DIM];        // w_o duplicated over K=4096 (hi|lo)
__device__ __align__(16) float  g_Yi [M_TOT*DIM];        // raw i   (later: h)
__device__ __align__(16) float  g_Yf [M_TOT*DIM];        // f = sigmoid(raw)
__device__ __align__(16) float  g_Yg [M_TOT*DIM];        // gsw = g*sigmoid(g)
__device__ __align__(16) __half g_A2 [M_TOT*2*DIM];      // (o*s_o) split hi|lo
__device__ float g_P [NCH*BATCH*DIM];
__device__ float g_Hc[NCH*BATCH*DIM];
__device__ float g_Cr[NCH*BATCH*DIM];

// ---------------- PTX helpers ----------------
__device__ __forceinline__ void cp16(uint32_t s, const void* g) {
    asm volatile("cp.async.cg.shared.global [%0], [%1], 16;\n" :: "r"(s), "l"(g));
}
__device__ __forceinline__ void cp_commit() { asm volatile("cp.async.commit_group;\n"); }
template<int N> __device__ __forceinline__ void cp_wait() {
    asm volatile("cp.async.wait_group %0;\n" :: "n"(N));
}
__device__ __forceinline__ void ldsm4(uint32_t& r0, uint32_t& r1, uint32_t& r2, uint32_t& r3, uint32_t a) {
    asm volatile("ldmatrix.sync.aligned.m8n8.x4.shared.b16 {%0,%1,%2,%3},[%4];\n"
                 : "=r"(r0), "=r"(r1), "=r"(r2), "=r"(r3) : "r"(a));
}
__device__ __forceinline__ void mma16816(float* c, const uint32_t* a, const uint32_t* b) {
    asm volatile("mma.sync.aligned.m16n8k16.row.col.f32.f16.f16.f32 "
                 "{%0,%1,%2,%3},{%4,%5,%6,%7},{%8,%9},{%0,%1,%2,%3};\n"
                 : "+f"(c[0]), "+f"(c[1]), "+f"(c[2]), "+f"(c[3])
                 : "r"(a[0]), "r"(a[1]), "r"(a[2]), "r"(a[3]), "r"(b[0]), "r"(b[1]));
}
// swizzled half-index inside a BMxBK stage (rows of 64 halfs = 8 chunks of 16B)
__device__ __forceinline__ uint32_t swz(int row, int k) {
    return (uint32_t)(row*BK + ((((k >> 3) ^ (row & 7)) << 3) | (k & 7)));
}
__device__ __forceinline__ float fsig(float x) {   // fast sigmoid via MUFU ex2 path
    return 1.f / (1.f + __expf(-x));
}

// ---------------- elementwise kernels ----------------
__global__ void k_quant(const float* __restrict__ hs) {
    int i = blockIdx.x * 256 + threadIdx.x;
    const float4 v = ((const float4*)hs)[i];
    __half h[4];
    h[0] = __float2half_rn(rintf(v.x * 256.f));
    h[1] = __float2half_rn(rintf(v.y * 256.f));
    h[2] = __float2half_rn(rintf(v.z * 256.f));
    h[3] = __float2half_rn(rintf(v.w * 256.f));
    ((uint2*)g_Xq)[i] = *(uint2*)h;
}

__global__ void k_transpose(const float* __restrict__ wi, const float* __restrict__ wf,
                            const float* __restrict__ wg) {
    __shared__ float tile[32][33];
    int z = blockIdx.z;
    const float* src = (z == 0) ? wi : (z == 1) ? wf : wg;
    __half* dst = (z == 0) ? g_Wi : (z == 1) ? g_Wf : g_Wg;
    int k0 = blockIdx.y * 32, n0 = blockIdx.x * 32;
    int tx = threadIdx.x, ty = threadIdx.y;     // 32 x 8
    #pragma unroll
    for (int j = 0; j < 32; j += 8)
        tile[ty + j][tx] = src[(size_t)(k0 + ty + j) * DIM + n0 + tx];
    __syncthreads();
    #pragma unroll
    for (int j = 0; j < 32; j += 8)
        dst[(size_t)(n0 + ty + j) * DIM + k0 + tx] = __float2half_rn(tile[tx][ty + j]);
}

__global__ void k_wo(const float* __restrict__ wo) {
    int idx = blockIdx.x * 256 + threadIdx.x;     // over DIM*DIM
    int n = idx >> 11, k = idx & 2047;
    __half h = __float2half_rn(wo[idx]);          // ternary: exact
    g_Wo2[(size_t)n * (2*DIM) + k]        = h;    // multiplies o_hi
    g_Wo2[(size_t)n * (2*DIM) + DIM + k]  = h;    // multiplies o_lo
}

// ---------------- GEMM: C[M,N] = A[M,K] * B[N,K]^T (fp16 in, fp32 acc) ----------------
// 4 warps, 64x64 warp tiles, 3-stage cp.async ring.
__global__ void __launch_bounds__(NTHREADS, 2) k_gemm(
    const __half* __restrict__ A,
    const __half* __restrict__ B0, const __half* __restrict__ B1,
    const __half* __restrict__ B2,
    float* C0, float* C1, float* C2,
    const float* s0, const float* s1, const float* s2,
    int K, int mode)
{
    extern __shared__ __half sm[];
    constexpr int STAGE_H = BM * BK + BN * BK;    // halfs per stage
    int z = blockIdx.z;
    const __half* Bw = (z == 0) ? B0 : (z == 1) ? B1 : B2;
    float* Cc        = (z == 0) ? C0 : (z == 1) ? C1 : C2;
    const float* sp  = (z == 0) ? s0 : (z == 1) ? s1 : s2;

    int bm = blockIdx.y * BM, bn = blockIdx.x * BN;
    const __half* Ag = A  + (size_t)bm * K;
    const __half* Bg = Bw + (size_t)bn * K;
    int tid = threadIdx.x;
    uint32_t sbase = (uint32_t)__cvta_generic_to_shared(sm);
    int KT = K / BK;

    int lane = tid & 31, w = tid >> 5;
    int wm = (w >> 1) * 64, wn = (w & 1) * 64;   // 2x2 warp grid, warp tile 64x64
    int g = lane >> 2, t2 = (lane & 3) << 1;
    int r = lane & 7, sub = lane >> 3;

    float acc[4][8][4];
    #pragma unroll
    for (int a = 0; a < 4; a++)
        #pragma unroll
        for (int b = 0; b < 8; b++)
            #pragma unroll
            for (int c = 0; c < 4; c++) acc[a][b][c] = 0.f;

    // stage loader: 128 threads, 8 x 16B each for A and B
    auto load = [&](int st, int kt) {
        int kb = kt * BK;
        uint32_t sA = sbase + (uint32_t)(st * STAGE_H) * 2;
        uint32_t sB = sA + (uint32_t)(BM * BK) * 2;
        #pragma unroll
        for (int i = 0; i < 8; i++) {
            int v = tid + i * NTHREADS;
            int row = v >> 3, ch = v & 7;
            uint32_t so = (uint32_t)(swz(row, ch * 8) * 2);
            cp16(sA + so, Ag + (size_t)row * K + kb + ch * 8);
            cp16(sB + so, Bg + (size_t)row * K + kb + ch * 8);
        }
    };

    // prologue: fill NSTAGE-1 stages
    load(0, 0); cp_commit();
    load(1, 1); cp_commit();

    for (int kt = 0; kt < KT; kt++) {
        cp_wait<NSTAGE - 2>();       // stage kt resident
        __syncthreads();
        if (kt + NSTAGE - 1 < KT) load((kt + NSTAGE - 1) % NSTAGE, kt + NSTAGE - 1);
        cp_commit();                 // uniform group counting

        int stb = (kt % NSTAGE) * STAGE_H;
        uint32_t sA = sbase + (uint32_t)stb * 2;
        uint32_t sB = sA + (uint32_t)(BM * BK) * 2;
        #pragma unroll
        for (int ks = 0; ks < 4; ks++) {
            int ko = ks * 16;
            uint32_t a[4][4], b[8][2];
            #pragma unroll
            for (int mi = 0; mi < 4; mi++) {
                int row = wm + mi * 16 + r + ((sub & 1) << 3);
                int kk  = ko + ((sub >> 1) << 3);
                ldsm4(a[mi][0], a[mi][1], a[mi][2], a[mi][3],
                      sA + (uint32_t)(swz(row, kk) * 2));
            }
            #pragma unroll
            for (int p = 0; p < 4; p++) {
                int rown = wn + p * 16 + r + ((sub >> 1) << 3);
                int kk   = ko + ((sub & 1) << 3);
                ldsm4(b[2*p][0], b[2*p][1], b[2*p+1][0], b[2*p+1][1],
                      sB + (uint32_t)(swz(rown, kk) * 2));
            }
            #pragma unroll
            for (int mi = 0; mi < 4; mi++)
                #pragma unroll
                for (int ni = 0; ni < 8; ni++)
                    mma16816(acc[mi][ni], a[mi], b[ni]);
        }
    }

    const float inv256 = 1.f / 256.f;
    #pragma unroll
    for (int mi = 0; mi < 4; mi++) {
        #pragma unroll
        for (int ni = 0; ni < 8; ni++) {
            int row = bm + wm + mi * 16 + g;
            int col = bn + wn + ni * 8 + t2;
            float* c = acc[mi][ni];
            if (mode == 0) {
                float sa = sp[col] * inv256, sb = sp[col + 1] * inv256;
                float v0 = c[0] * sa, v1 = c[1] * sb, v2 = c[2] * sa, v3 = c[3] * sb;
                if (z == 1) {          // forget gate: store sigmoid
                    v0 = fsig(v0); v1 = fsig(v1); v2 = fsig(v2); v3 = fsig(v3);
                } else if (z == 2) {   // output gate: store swish
                    v0 = v0 * fsig(v0); v1 = v1 * fsig(v1);
                    v2 = v2 * fsig(v2); v3 = v3 * fsig(v3);
                }
                Cc[(size_t)row * DIM + col]           = v0;
                Cc[(size_t)row * DIM + col + 1]       = v1;
                Cc[(size_t)(row + 8) * DIM + col]     = v2;
                Cc[(size_t)(row + 8) * DIM + col + 1] = v3;
            } else {  // to_fixed(acc)
                Cc[(size_t)row * DIM + col]           = rintf(c[0] * 256.f) * inv256;
                Cc[(size_t)row * DIM + col + 1]       = rintf(c[1] * 256.f) * inv256;
                Cc[(size_t)(row + 8) * DIM + col]     = rintf(c[2] * 256.f) * inv256;
                Cc[(size_t)(row + 8) * DIM + col + 1] = rintf(c[3] * 256.f) * inv256;
            }
        }
    }
}

// ---------------- chunked linear-recurrence scan (f precomputed) ----------------
__global__ void k_scan1() {
    int d4 = blockIdx.x * 128 + threadIdx.x;        // float4 index within DIM/4
    int c = blockIdx.y, b = blockIdx.z;
    size_t base = ((size_t)(b * SEQ + c * CHLEN)) * (DIM/4) + d4;
    const float4* Yf4 = (const float4*)g_Yf;
    const float4* Yi4 = (const float4*)g_Yi;
    float4 P = make_float4(1.f,1.f,1.f,1.f), H = make_float4(0.f,0.f,0.f,0.f);
    #pragma unroll 4
    for (int t = 0; t < CHLEN; t++) {
        float4 f  = Yf4[base + (size_t)t * (DIM/4)];
        float4 yi = Yi4[base + (size_t)t * (DIM/4)];
        P.x *= f.x; P.y *= f.y; P.z *= f.z; P.w *= f.w;
        H.x = fmaf(f.x, H.x, (1.f - f.x) * yi.x);
        H.y = fmaf(f.y, H.y, (1.f - f.y) * yi.y);
        H.z = fmaf(f.z, H.z, (1.f - f.z) * yi.z);
        H.w = fmaf(f.w, H.w, (1.f - f.w) * yi.w);
    }
    int o = (c * BATCH + b) * (DIM/4) + d4;
    ((float4*)g_P)[o] = P; ((float4*)g_Hc)[o] = H;
}

__global__ void k_scan2() {
    int idx = blockIdx.x * 256 + threadIdx.x;   // 0..B*DIM/4-1
    float4 h = make_float4(0.f,0.f,0.f,0.f);
    #pragma unroll 8
    for (int c = 0; c < NCH; c++) {
        int o = c * (BATCH * DIM / 4) + idx;
        ((float4*)g_Cr)[o] = h;
        float4 P = ((const float4*)g_P)[o];
        float4 Hc = ((const float4*)g_Hc)[o];
        h.x = fmaf(P.x, h.x, Hc.x); h.y = fmaf(P.y, h.y, Hc.y);
        h.z = fmaf(P.z, h.z, Hc.z); h.w = fmaf(P.w, h.w, Hc.w);
    }
}

__global__ void k_scan3() {
    int d4 = blockIdx.x * 128 + threadIdx.x;
    int c = blockIdx.y, b = blockIdx.z;
    size_t base = ((size_t)(b * SEQ + c * CHLEN)) * (DIM/4) + d4;
    const float4* Yf4 = (const float4*)g_Yf;
    float4* Yi4 = (float4*)g_Yi;
    float4 h = ((const float4*)g_Cr)[(c * BATCH + b) * (DIM/4) + d4];
    #pragma unroll 4
    for (int t = 0; t < CHLEN; t++) {
        float4 f  = Yf4[base + (size_t)t * (DIM/4)];
        float4 yi = Yi4[base + (size_t)t * (DIM/4)];
        h.x = fmaf(f.x, h.x, (1.f - f.x) * yi.x);
        h.y = fmaf(f.y, h.y, (1.f - f.y) * yi.y);
        h.z = fmaf(f.z, h.z, (1.f - f.z) * yi.z);
        h.w = fmaf(f.w, h.w, (1.f - f.w) * yi.w);
        Yi4[base + (size_t)t * (DIM/4)] = h;   // overwrite i-buffer with h
    }
}

// ---------------- RMSNorm * weight * gsw * s_o -> hi/lo fp16 split ----------------
__global__ void k_norm(const float* __restrict__ so, const float* __restrict__ gnw) {
    int m = blockIdx.x;
    int tid = threadIdx.x;
    size_t b4 = (size_t)m * (DIM/4);
    const float4* Yi4 = (const float4*)g_Yi;
    float4 hv[2];
    float ss = 0.f;
    #pragma unroll
    for (int j = 0; j < 2; j++) {
        hv[j] = Yi4[b4 + tid + j * 256];
        ss += hv[j].x*hv[j].x + hv[j].y*hv[j].y + hv[j].z*hv[j].z + hv[j].w*hv[j].w;
    }
    #pragma unroll
    for (int o = 16; o; o >>= 1) ss += __shfl_xor_sync(0xffffffffu, ss, o);
    __shared__ float red[8];
    __shared__ float tot;
    if ((tid & 31) == 0) red[tid >> 5] = ss;
    __syncthreads();
    if (tid < 8) {
        float v = red[tid];
        #pragma unroll
        for (int o = 4; o; o >>= 1) v += __shfl_xor_sync(0xffu, v, o);
        if (tid == 0) tot = v;
    }
    __syncthreads();
    float rms = rsqrtf(tot * (1.f / DIM) + 1e-5f);
    const float4* Yg4 = (const float4*)g_Yg;
    const float4* so4 = (const float4*)so;
    const float4* gn4 = (const float4*)gnw;
    #pragma unroll
    for (int j = 0; j < 2; j++) {
        int e4 = tid + j * 256;
        float4 gv = Yg4[b4 + e4];      // already g*sigmoid(g)
        float4 sv = so4[e4];
        float4 wv = gn4[e4];
        float q[4];
        q[0] = hv[j].x * rms * wv.x * gv.x * sv.x;
        q[1] = hv[j].y * rms * wv.y * gv.y * sv.y;
        q[2] = hv[j].z * rms * wv.z * gv.z * sv.z;
        q[3] = hv[j].w * rms * wv.w * gv.w * sv.w;
        __half hi[4]; __half lo[4];
        #pragma unroll
        for (int u = 0; u < 4; u++) {
            hi[u] = __float2half_rn(q[u]);
            lo[u] = __float2half_rn(q[u] - __half2float(hi[u]));
        }
        ((uint2*)(g_A2 + (size_t)m * (2*DIM)))[e4]            = *(uint2*)hi;
        ((uint2*)(g_A2 + (size_t)m * (2*DIM) + DIM))[e4]      = *(uint2*)lo;
    }
}

// ---------------- launch ----------------
extern "C" void kernel_launch(void* const* d_in, const int* in_sizes, int n_in,
                              void* d_out, int out_size) {
    const float* hs  = (const float*)d_in[0];
    const float* wi  = (const float*)d_in[1];
    const float* wf  = (const float*)d_in[2];
    const float* wg  = (const float*)d_in[3];
    const float* wo  = (const float*)d_in[4];
    const float* si  = (const float*)d_in[5];
    const float* sf  = (const float*)d_in[6];
    const float* sg  = (const float*)d_in[7];
    const float* so  = (const float*)d_in[8];
    const float* gnw = (const float*)d_in[9];

    __half *Xq, *Wi, *Wf, *Wg, *Wo2, *A2;
    float  *Yi, *Yf, *Yg;
    cudaGetSymbolAddress((void**)&Xq,  g_Xq);
    cudaGetSymbolAddress((void**)&Wi,  g_Wi);
    cudaGetSymbolAddress((void**)&Wf,  g_Wf);
    cudaGetSymbolAddress((void**)&Wg,  g_Wg);
    cudaGetSymbolAddress((void**)&Wo2, g_Wo2);
    cudaGetSymbolAddress((void**)&A2,  g_A2);
    cudaGetSymbolAddress((void**)&Yi,  g_Yi);
    cudaGetSymbolAddress((void**)&Yf,  g_Yf);
    cudaGetSymbolAddress((void**)&Yg,  g_Yg);

    const int smem = NSTAGE * (BM * BK + BN * BK) * 2;  // 96 KB
    cudaFuncSetAttribute(k_gemm, cudaFuncAttributeMaxDynamicSharedMemorySize, smem);

    k_quant<<<(M_TOT * DIM) / 1024, 256>>>(hs);
    k_transpose<<<dim3(DIM / 32, DIM / 32, 3), dim3(32, 8)>>>(wi, wf, wg);
    k_wo<<<(DIM * DIM) / 256, 256>>>(wo);

    // i/f/g projections: exact integer fp16 MMA; epilogue applies scale + sigmoid/swish
    k_gemm<<<dim3(DIM / BN, M_TOT / BM, 3), NTHREADS, smem>>>(
        Xq, Wi, Wf, Wg, Yi, Yf, Yg, si, sf, sg, DIM, 0);

    k_scan1<<<dim3(DIM / 512, NCH, BATCH), 128>>>();
    k_scan2<<<(BATCH * DIM / 4) / 256, 256>>>();
    k_scan3<<<dim3(DIM / 512, NCH, BATCH), 128>>>();

    k_norm<<<M_TOT, 256>>>(so, gnw);

    // output projection: split-fp16 (hi+lo), K_eff = 4096, to_fixed epilogue
    k_gemm<<<dim3(DIM / BN, M_TOT / BM, 1), NTHREADS, smem>>>(
        A2, Wo2, Wo2, Wo2, (float*)d_out, nullptr, nullptr,
        nullptr, nullptr, nullptr, 2 * DIM, 1);
}